// round 1
// baseline (speedup 1.0000x reference)
#include <cuda_runtime.h>

#define C       128
#define ALPHA   0.25f
#define WARPS_PER_BLOCK 8
#define THREADS (WARPS_PER_BLOCK * 32)

// Global accumulator (device scratch; zeroed by a kernel every launch so the
// graph replays deterministically).
__device__ double g_sum;

__global__ void fl_zero_kernel() { g_sum = 0.0; }

__global__ __launch_bounds__(THREADS) void fl_main_kernel(
    const float* __restrict__ preds,
    const int*   __restrict__ labels,
    int n_rows)
{
    const int lane = threadIdx.x & 31;
    const int warp_in_block = threadIdx.x >> 5;
    const int row = blockIdx.x * WARPS_PER_BLOCK + warp_in_block;

    __shared__ float partial[WARPS_PER_BLOCK];

    float per_row = 0.0f;

    if (row < n_rows) {
        // Each lane handles 4 contiguous columns: one float4 + one int4,
        // warp covers the whole 128-wide row (512B coalesced per operand).
        const long long base = (long long)row * C + lane * 4;
        const float4 p = *reinterpret_cast<const float4*>(preds + base);
        const int4  l = *reinterpret_cast<const int4*>(labels + base);

        // sum of exp (unstabilized, matches reference; preds ~ N(0,1), safe)
        float se = __expf(p.x) + __expf(p.y) + __expf(p.z) + __expf(p.w);

        // one-hot gather in integer domain: exactly one label==1 across the
        // row, so the integer sum of label*bits(pred) is the labeled logit's
        // bit pattern. Avoids per-element int->float conversion.
        int lb = l.x * __float_as_int(p.x)
               + l.y * __float_as_int(p.y)
               + l.z * __float_as_int(p.z)
               + l.w * __float_as_int(p.w);

        // warp butterfly reduction
        #pragma unroll
        for (int off = 16; off; off >>= 1) {
            se += __shfl_xor_sync(0xffffffffu, se, off);
            lb += __shfl_xor_sync(0xffffffffu, lb, off);
        }

        if (lane == 0) {
            const float t1  = se;
            const float lbl = __int_as_float(lb);   // label logit
            const float pgt = __expf(lbl) / t1;     // p = exp(lbl)/sumexp
            const float om  = 1.0f - pgt;
            // t2 + log(t1) = log(t1) - lbl
            per_row = ALPHA * om * om * (__logf(t1) - lbl);
        }
    }

    if (lane == 0) partial[warp_in_block] = per_row;
    __syncthreads();

    if (threadIdx.x == 0) {
        float s = 0.0f;
        #pragma unroll
        for (int i = 0; i < WARPS_PER_BLOCK; i++) s += partial[i];
        atomicAdd(&g_sum, (double)s);
    }
}

__global__ void fl_finalize_kernel(float* __restrict__ out, int n_rows)
{
    out[0] = (float)(g_sum / (double)n_rows);
}

extern "C" void kernel_launch(void* const* d_in, const int* in_sizes, int n_in,
                              void* d_out, int out_size)
{
    const float* preds  = (const float*)d_in[0];
    const int*   labels = (const int*)d_in[1];
    float* out = (float*)d_out;

    const int n_rows = in_sizes[0] / C;
    const int blocks = (n_rows + WARPS_PER_BLOCK - 1) / WARPS_PER_BLOCK;

    fl_zero_kernel<<<1, 1>>>();
    fl_main_kernel<<<blocks, THREADS>>>(preds, labels, n_rows);
    fl_finalize_kernel<<<1, 1>>>(out, n_rows);
}

// round 2
// speedup vs baseline: 2.4683x; 2.4683x over previous
#include <cuda_runtime.h>

#define C       128
#define ALPHA   0.25f
#define WARPS_PER_BLOCK 8
#define THREADS (WARPS_PER_BLOCK * 32)
#define UNROLL  4
#define GRID_BLOCKS 2368   // 148 SMs * 16 blocks

__device__ double g_sum;

__global__ void fl_zero_kernel() { g_sum = 0.0; }

__global__ __launch_bounds__(THREADS) void fl_main_kernel(
    const float* __restrict__ preds,
    const int*   __restrict__ labels,
    int n_rows)
{
    const int lane   = threadIdx.x & 31;
    const int warp   = threadIdx.x >> 5;
    const int gwarp  = blockIdx.x * WARPS_PER_BLOCK + warp;
    const int nwarps = gridDim.x * WARPS_PER_BLOCK;

    __shared__ float partial[WARPS_PER_BLOCK];

    float acc = 0.0f;   // identical across lanes after butterfly; lane0 commits

    const int n_groups = n_rows / UNROLL;

    for (int g = gwarp; g < n_groups; g += nwarps) {
        const long long base = ((long long)g * UNROLL) * C + lane * 4;

        // Front-batch 8 independent LDG.128s (high MLP before first use).
        float4 p[UNROLL];
        int4   l[UNROLL];
        #pragma unroll
        for (int u = 0; u < UNROLL; u++)
            p[u] = *reinterpret_cast<const float4*>(preds + base + u * C);
        #pragma unroll
        for (int u = 0; u < UNROLL; u++)
            l[u] = *reinterpret_cast<const int4*>(labels + base + u * C);

        float se[UNROLL];
        int   lb[UNROLL];
        #pragma unroll
        for (int u = 0; u < UNROLL; u++) {
            se[u] = __expf(p[u].x) + __expf(p[u].y)
                  + __expf(p[u].z) + __expf(p[u].w);
            lb[u] = l[u].x * __float_as_int(p[u].x)
                  + l[u].y * __float_as_int(p[u].y)
                  + l[u].z * __float_as_int(p[u].z)
                  + l[u].w * __float_as_int(p[u].w);
        }

        // Butterfly reductions, interleaved across the 4 rows for ILP.
        #pragma unroll
        for (int off = 16; off; off >>= 1) {
            #pragma unroll
            for (int u = 0; u < UNROLL; u++) {
                se[u] += __shfl_xor_sync(0xffffffffu, se[u], off);
                lb[u] += __shfl_xor_sync(0xffffffffu, lb[u], off);
            }
        }

        #pragma unroll
        for (int u = 0; u < UNROLL; u++) {
            const float t1  = se[u];
            const float lbl = __int_as_float(lb[u]);   // labeled logit
            const float pgt = __expf(lbl) / t1;
            const float om  = 1.0f - pgt;
            acc += ALPHA * om * om * (__logf(t1) - lbl);
        }
    }

    // Tail rows (n_rows not divisible by UNROLL) — warp-per-row.
    for (int r = n_groups * UNROLL + gwarp; r < n_rows; r += nwarps) {
        const long long base = (long long)r * C + lane * 4;
        const float4 p = *reinterpret_cast<const float4*>(preds + base);
        const int4   l = *reinterpret_cast<const int4*>(labels + base);
        float se = __expf(p.x) + __expf(p.y) + __expf(p.z) + __expf(p.w);
        int   lb = l.x * __float_as_int(p.x) + l.y * __float_as_int(p.y)
                 + l.z * __float_as_int(p.z) + l.w * __float_as_int(p.w);
        #pragma unroll
        for (int off = 16; off; off >>= 1) {
            se += __shfl_xor_sync(0xffffffffu, se, off);
            lb += __shfl_xor_sync(0xffffffffu, lb, off);
        }
        const float lbl = __int_as_float(lb);
        const float pgt = __expf(lbl) / se;
        const float om  = 1.0f - pgt;
        acc += ALPHA * om * om * (__logf(se) - lbl);
    }

    if (lane == 0) partial[warp] = acc;
    __syncthreads();

    if (threadIdx.x == 0) {
        float s = 0.0f;
        #pragma unroll
        for (int i = 0; i < WARPS_PER_BLOCK; i++) s += partial[i];
        atomicAdd(&g_sum, (double)s);
    }
}

__global__ void fl_finalize_kernel(float* __restrict__ out, int n_rows)
{
    out[0] = (float)(g_sum / (double)n_rows);
}

extern "C" void kernel_launch(void* const* d_in, const int* in_sizes, int n_in,
                              void* d_out, int out_size)
{
    const float* preds  = (const float*)d_in[0];
    const int*   labels = (const int*)d_in[1];
    float* out = (float*)d_out;

    const int n_rows = in_sizes[0] / C;

    fl_zero_kernel<<<1, 1>>>();
    fl_main_kernel<<<GRID_BLOCKS, THREADS>>>(preds, labels, n_rows);
    fl_finalize_kernel<<<1, 1>>>(out, n_rows);
}